// round 6
// baseline (speedup 1.0000x reference)
#include <cuda_runtime.h>
#include <cuda_bf16.h>
#include <math.h>

// Problem dims
#define BB 128
#define TT 128
#define VV 1024
#define EE 512
#define HH 1024
#define GG 4096   // 4*H

// d_out layout (floats): decoder_outputs [B,T,H], hf [B,H], cf [B,H], symbols [B,T]
#define OUT_DEC 0
#define OUT_HF  (BB*TT*HH)
#define OUT_CF  (OUT_HF + BB*HH)
#define OUT_SYM (OUT_CF + BB*HH)

#define NCTA 128
#define NTHR 512

// ---------------- scratch (static device memory) ----------------
__device__ float g_dec_table[VV * GG];      // emb @ dec_W_ih^T + dec_b
__device__ float g_pregates_enc[TT * GG];   // row-127 enc input pregates
__device__ float g_he[2][HH];
__device__ float g_ce[HH];
__device__ float g_hd[2][BB * HH];          // decoder h, [b][k], double buffered
__device__ float g_cd[BB * HH];             // decoder c, [b][j]
__device__ unsigned long long g_amax[2][BB];
__device__ int   g_idx64;
__device__ unsigned g_bar_count = 0;
__device__ unsigned g_bar_gen = 0;

// ---------------- helpers ----------------
__device__ __forceinline__ int read_idx(const void* p, int i) {
    if (g_idx64) return (int)((const long long*)p)[i];
    return ((const int*)p)[i];
}
__device__ __forceinline__ float sigf(float x) { return 1.0f / (1.0f + expf(-x)); }

__device__ __forceinline__ void ffma2(unsigned long long& d, unsigned long long a, unsigned long long b) {
    asm("fma.rn.f32x2 %0, %1, %2, %0;" : "+l"(d) : "l"(a), "l"(b));
}
__device__ __forceinline__ unsigned long long dupf(float x) {
    unsigned long long r; unsigned u = __float_as_uint(x);
    asm("mov.b64 %0, {%1, %1};" : "=l"(r) : "r"(u));
    return r;
}
__device__ __forceinline__ float lo2(unsigned long long p) { return __uint_as_float((unsigned)p); }
__device__ __forceinline__ float hi2(unsigned long long p) { return __uint_as_float((unsigned)(p >> 32)); }
__device__ __forceinline__ unsigned monof(float v) {
    unsigned b = __float_as_uint(v);
    return b ^ ((b & 0x80000000u) ? 0xFFFFFFFFu : 0x80000000u);
}

// grid barrier: release/acquire gpu scope (all 128 CTAs resident: 1 per SM)
__device__ __forceinline__ void grid_bar() {
    __syncthreads();
    if (threadIdx.x == 0) {
        unsigned gen;
        asm volatile("ld.acquire.gpu.u32 %0, [%1];" : "=r"(gen) : "l"(&g_bar_gen));
        unsigned old;
        asm volatile("atom.add.release.gpu.u32 %0, [%1], 1;" : "=r"(old) : "l"(&g_bar_count));
        if (old == NCTA - 1) {
            g_bar_count = 0;
            asm volatile("st.release.gpu.u32 [%0], %1;" :: "l"(&g_bar_gen), "r"(gen + 1));
        } else {
            unsigned cur;
            do {
                asm volatile("ld.acquire.gpu.u32 %0, [%1];" : "=r"(cur) : "l"(&g_bar_gen));
            } while (cur == gen);
        }
    }
    __syncthreads();
}

// Detect input index dtype
__global__ void detect_kernel(const void* p) {
    if (threadIdx.x == 0) {
        const unsigned long long* q = (const unsigned long long*)p;
        int ok = 1;
        for (int i = 0; i < 8; i++) if (q[i] > 1023ull) ok = 0;
        g_idx64 = ok;
    }
}

// ---------------- table GEMM (one-time) — unchanged from R3 (bit-exact lineage) ----------------
__device__ __forceinline__ void table_gemm_body(
    const float* __restrict__ A, const float* __restrict__ W,
    const float* __restrict__ bias, float* __restrict__ C,
    int K, const void* map, int map_off)
{
    __shared__ __align__(16) float Ash[16][68];
    __shared__ __align__(16) float Bsh[16][68];
    int tid = threadIdx.x;
    int tm = tid & 15, tn = tid >> 4;
    int n0 = blockIdx.x * 64, m0 = blockIdx.y * 64;

    int r  = tid >> 2;
    int kf = (tid & 3) << 2;
    int am = m0 + r;
    int arow = am;
    if (map) arow = read_idx(map, map_off + am);
    const float* Aptr = A + (size_t)arow * K;
    const float* Wptr = W + (size_t)(n0 + r) * K;

    unsigned long long accp[4][2];
#pragma unroll
    for (int i = 0; i < 4; i++) { accp[i][0] = 0ull; accp[i][1] = 0ull; }

    for (int k0 = 0; k0 < K; k0 += 16) {
        float4 av = *(const float4*)(Aptr + k0 + kf);
        float4 bv = *(const float4*)(Wptr + k0 + kf);
        __syncthreads();
        Ash[kf+0][r] = av.x; Ash[kf+1][r] = av.y; Ash[kf+2][r] = av.z; Ash[kf+3][r] = av.w;
        Bsh[kf+0][r] = bv.x; Bsh[kf+1][r] = bv.y; Bsh[kf+2][r] = bv.z; Bsh[kf+3][r] = bv.w;
        __syncthreads();
#pragma unroll
        for (int k = 0; k < 16; k++) {
            float4 a4 = *(const float4*)&Ash[k][tm * 4];
            ulonglong2 b01 = *(const ulonglong2*)&Bsh[k][tn * 4];
            unsigned long long a0 = dupf(a4.x), a1 = dupf(a4.y), a2 = dupf(a4.z), a3 = dupf(a4.w);
            ffma2(accp[0][0], b01.x, a0); ffma2(accp[0][1], b01.y, a0);
            ffma2(accp[1][0], b01.x, a1); ffma2(accp[1][1], b01.y, a1);
            ffma2(accp[2][0], b01.x, a2); ffma2(accp[2][1], b01.y, a2);
            ffma2(accp[3][0], b01.x, a3); ffma2(accp[3][1], b01.y, a3);
        }
    }
#pragma unroll
    for (int i = 0; i < 4; i++) {
        int m = m0 + tm * 4 + i;
#pragma unroll
        for (int p = 0; p < 2; p++) {
            int n = n0 + tn * 4 + p * 2;
            C[(size_t)m * GG + n]     = lo2(accp[i][p]) + bias[n];
            C[(size_t)m * GG + n + 1] = hi2(accp[i][p]) + bias[n + 1];
        }
    }
}

__global__ __launch_bounds__(256) void table_dec_kernel(
    const float* __restrict__ emb, const float* __restrict__ W, const float* __restrict__ bias)
{
    table_gemm_body(emb, W, bias, g_dec_table, EE, nullptr, 0);
}
__global__ __launch_bounds__(256) void table_pre_kernel(
    const float* __restrict__ emb, const float* __restrict__ W, const float* __restrict__ bias,
    const void* __restrict__ inputs)
{
    table_gemm_body(emb, W, bias, g_pregates_enc, EE, inputs, 127 * TT);
}

// ---------------- persistent main kernel ----------------
// smem: buf = union{ gates w-tile [128][33] (4224f), gates staging gsh [128][34] (4352f),
//                    fc w-tile [32][33] (1056f) }  — phases separated by syncs
//       hsh [32][36] shared h^T chunk (both halves read it)
struct MainSmem {
    __align__(16) float buf[128 * 34];   // 4352 floats
    __align__(16) float hsh[32][36];     // 1152 floats
    int ssym[32];
};

__global__ __launch_bounds__(NTHR, 1) void main_kernel(
    const void* __restrict__ inputs,
    const float* __restrict__ eWhh,
    const float* __restrict__ dWhh,
    const float* __restrict__ fcW,
    const float* __restrict__ fcb,
    float* __restrict__ out)
{
    __shared__ MainSmem smem;
    const int cta = blockIdx.x;
    const int tid = threadIdx.x;
    const int half = tid >> 8;           // 0/1: column-half (gates) / b-half (fc)
    const int htid = tid & 255;

    // ---- phase 0: zero encoder state ----
    if (cta == 0) {
        for (int i = tid; i < HH; i += NTHR) { g_he[0][i] = 0.0f; g_ce[i] = 0.0f; }
    }
    grid_bar();

    // ---- encoder: batch row 127 only (first 8 warps compute; all hit grid_bar) ----
    {
        const int wid = tid >> 5, lane = tid & 31;
        const int j = cta * 8 + wid;
        const float* w = eWhh + (size_t)j * HH;
        for (int t = 0; t < TT; t++) {
            if (wid < 8) {
                const float* hin = g_he[t & 1];
                float a0 = 0.f, a1 = 0.f, a2 = 0.f, a3 = 0.f;
#pragma unroll 4
                for (int k = lane; k < HH; k += 32) {
                    float hv = hin[k];
                    a0 += hv * w[k];
                    a1 += hv * w[1024 * 1024 + k];
                    a2 += hv * w[2 * 1024 * 1024 + k];
                    a3 += hv * w[3 * 1024 * 1024 + k];
                }
#pragma unroll
                for (int o = 16; o; o >>= 1) {
                    a0 += __shfl_xor_sync(0xffffffffu, a0, o);
                    a1 += __shfl_xor_sync(0xffffffffu, a1, o);
                    a2 += __shfl_xor_sync(0xffffffffu, a2, o);
                    a3 += __shfl_xor_sync(0xffffffffu, a3, o);
                }
                if (lane == 0) {
                    const float* pg = g_pregates_enc + (size_t)t * GG;
                    float gi = a0 + pg[j];
                    float gf = a1 + pg[HH + j];
                    float gg = a2 + pg[2 * HH + j];
                    float go = a3 + pg[3 * HH + j];
                    float i_ = sigf(gi), f_ = sigf(gf), c_ = tanhf(gg), o_ = sigf(go);
                    float c = f_ * g_ce[j] + i_ * c_;
                    g_ce[j] = c;
                    g_he[(t + 1) & 1][j] = o_ * tanhf(c);
                }
            }
            grid_bar();
        }
    }

    // ---- decoder init ----
    {
        int base = cta * 1024 + tid * 2;
#pragma unroll
        for (int q = 0; q < 2; q++) {
            int k = tid * 2 + q;
            g_hd[0][base + q] = (cta == 127) ? g_he[0][k] : 0.0f;
            g_cd[base + q]    = (cta == 127) ? g_ce[k]    : 0.0f;
        }
    }
    grid_bar();

    // ---- decoder: 128 steps ----
    const int j0 = (cta & 31) * 32;          // gates j-tile / fc n-tile
    const int b0 = (cta >> 5) * 32;          // b-tile

    // gates mapping: thread owns 1 column (of 128) x 8 b's; full K sequential.
    const int col = half * 64 + (htid & 63); // 0..127
    const int bo  = htid >> 6;               // 0..3 (warp-uniform b-octet)
    // shared-chunk loader mapping
    const int hb = tid >> 3;                 // used when tid<256: 0..31
    const int hk = (tid & 7) << 2;
    // fc mapping: thread owns n=lane, 2 b's in its half's 16-row range.
    const int fn = tid & 31;                 // lane = n within tile
    const int bh = htid >> 5;                // 0..7 (warp-uniform)

    float* wsh = smem.buf;                   // gates w [col][33] / fc w [n][33]
    float* gsh = smem.buf;                   // gates staging [col][34] (after w dead)
    float* hshp = &smem.hsh[0][0];

    for (int t = 0; t < TT; t++) {
        // ===== gates phase: pregate = dec_table[sym] + h @ W_hh^T =====
        {
            const float* hin = g_hd[t & 1];
            float* hout = g_hd[(t + 1) & 1];

            if (tid < 32) {
                int b = b0 + tid;
                int s;
                if (t == 0) {
                    s = read_idx(inputs, b * TT);
                } else {
                    unsigned long long key = g_amax[(t - 1) & 1][b];
                    s = (int)(~(unsigned)key & 1023u);
                    if ((cta & 31) == 0) out[OUT_SYM + b * TT + (t - 1)] = (float)s;
                }
                smem.ssym[tid] = s;
            }
            if (cta == 0 && tid < BB) g_amax[t & 1][tid] = 0ull;

            unsigned long long acc[4] = {0ull, 0ull, 0ull, 0ull};

            float4 wreg[2];
            float4 hreg;
#pragma unroll
            for (int i = 0; i < 2; i++) {
                int q = i * 512 + tid;
                int c = q >> 3; int ks = (q & 7) << 2;
                int g = c >> 5, jj = c & 31;
                wreg[i] = *(const float4*)(dWhh + ((size_t)(g * HH + j0 + jj)) * HH + ks);
            }
            if (tid < 256) hreg = *(const float4*)(hin + (size_t)(b0 + hb) * HH + hk);

            const float* hbase = hshp + bo * 8;
            const float* wcol = wsh + col * 33;

            for (int ch = 0; ch < 32; ch++) {
                __syncthreads();
#pragma unroll
                for (int i = 0; i < 2; i++) {
                    int q = i * 512 + tid;
                    int c = q >> 3; int ks = (q & 7) << 2;
                    float* p = wsh + c * 33 + ks;
                    p[0] = wreg[i].x; p[1] = wreg[i].y; p[2] = wreg[i].z; p[3] = wreg[i].w;
                }
                if (tid < 256) {
                    float* p = hshp + hk * 36 + hb;
                    p[0] = hreg.x; p[36] = hreg.y; p[72] = hreg.z; p[108] = hreg.w;
                }
                if (ch < 31) {
                    int k0 = (ch + 1) * 32;
#pragma unroll
                    for (int i = 0; i < 2; i++) {
                        int q = i * 512 + tid;
                        int c = q >> 3; int ks = (q & 7) << 2;
                        int g = c >> 5, jj = c & 31;
                        wreg[i] = *(const float4*)(dWhh + ((size_t)(g * HH + j0 + jj)) * HH + k0 + ks);
                    }
                    if (tid < 256) hreg = *(const float4*)(hin + (size_t)(b0 + hb) * HH + k0 + hk);
                }
                __syncthreads();
#pragma unroll
                for (int k = 0; k < 32; k++) {
                    ulonglong2 h01 = *(const ulonglong2*)(hbase + k * 36);
                    ulonglong2 h23 = *(const ulonglong2*)(hbase + k * 36 + 4);
                    unsigned long long w = dupf(wcol[k]);
                    ffma2(acc[0], h01.x, w); ffma2(acc[1], h01.y, w);
                    ffma2(acc[2], h23.x, w); ffma2(acc[3], h23.y, w);
                }
            }

            // stage pre-activations [col][b] (w-tile dead)
            __syncthreads();
#pragma unroll
            for (int bp = 0; bp < 4; bp++) {
                *(unsigned long long*)(gsh + col * 34 + bo * 8 + 2 * bp) = acc[bp];
            }
            __syncthreads();

            // LSTM epilogue: 512 threads, each 2 b's
            {
                int jj = tid & 31;
                int grp = tid >> 5;               // 0..15
                int jg = j0 + jj;
#pragma unroll
                for (int i = 0; i < 2; i++) {
                    int b = grp * 2 + i;
                    int s = smem.ssym[b];
                    const float* tb = g_dec_table + (size_t)s * GG + jg;
                    float gi = gsh[(0 * 32 + jj) * 34 + b] + tb[0];
                    float gf = gsh[(1 * 32 + jj) * 34 + b] + tb[HH];
                    float gg = gsh[(2 * 32 + jj) * 34 + b] + tb[2 * HH];
                    float go = gsh[(3 * 32 + jj) * 34 + b] + tb[3 * HH];
                    float i_ = sigf(gi), f_ = sigf(gf), c_ = tanhf(gg), o_ = sigf(go);
                    int off = (b0 + b) * HH + jg;
                    float c = f_ * g_cd[off] + i_ * c_;
                    g_cd[off] = c;
                    hout[off] = o_ * tanhf(c);
                }
            }
        }
        grid_bar();

        // ===== fc phase: logits = h @ fc_W^T + fc_b; write + argmax =====
        {
            const float* h = g_hd[(t + 1) & 1];
            unsigned long long acc = 0ull;

            // loaders: tid<256 -> w tile; tid>=256 -> h tile
            float4 ldreg;
            if (tid < 256) {
                int wn = tid >> 3, wk = (tid & 7) << 2;
                ldreg = *(const float4*)(fcW + (size_t)(j0 + wn) * HH + wk);
            } else {
                int ht = tid - 256;
                int lb = ht >> 3, lk = (ht & 7) << 2;
                ldreg = *(const float4*)(h + (size_t)(b0 + lb) * HH + lk);
            }

            const float* hbase = hshp + half * 16 + bh * 2;
            const float* wp = wsh + fn * 33;

            for (int ch = 0; ch < 32; ch++) {
                __syncthreads();
                if (tid < 256) {
                    int wn = tid >> 3, wk = (tid & 7) << 2;
                    float* p = wsh + wn * 33 + wk;
                    p[0] = ldreg.x; p[1] = ldreg.y; p[2] = ldreg.z; p[3] = ldreg.w;
                } else {
                    int ht = tid - 256;
                    int lb = ht >> 3, lk = (ht & 7) << 2;
                    float* p = hshp + lk * 36 + lb;
                    p[0] = ldreg.x; p[36] = ldreg.y; p[72] = ldreg.z; p[108] = ldreg.w;
                }
                if (ch < 31) {
                    int k0 = (ch + 1) * 32;
                    if (tid < 256) {
                        int wn = tid >> 3, wk = (tid & 7) << 2;
                        ldreg = *(const float4*)(fcW + (size_t)(j0 + wn) * HH + k0 + wk);
                    } else {
                        int ht = tid - 256;
                        int lb = ht >> 3, lk = (ht & 7) << 2;
                        ldreg = *(const float4*)(h + (size_t)(b0 + lb) * HH + k0 + lk);
                    }
                }
                __syncthreads();
#pragma unroll
                for (int k = 0; k < 32; k++) {
                    unsigned long long hp = *(const unsigned long long*)(hbase + k * 36);
                    unsigned long long wd = dupf(wp[k]);
                    ffma2(acc, hp, wd);
                }
            }

            int n = j0 + fn;
            float bias = fcb[n];
            float v[2] = { lo2(acc) + bias, hi2(acc) + bias };
#pragma unroll
            for (int i = 0; i < 2; i++) {
                int b = b0 + half * 16 + bh * 2 + i;
                out[OUT_DEC + (size_t)b * TT * HH + (size_t)t * HH + n] = v[i];
            }
#pragma unroll
            for (int i = 0; i < 2; i++) {
                unsigned long long key =
                    ((unsigned long long)monof(v[i]) << 32) | (unsigned)(~(unsigned)n);
#pragma unroll
                for (int off = 16; off; off >>= 1) {
                    unsigned long long o = __shfl_xor_sync(0xffffffffu, key, off);
                    if (o > key) key = o;
                }
                if (fn == 0) atomicMax(&g_amax[t & 1][b0 + half * 16 + bh * 2 + i], key);
            }
        }
        grid_bar();
    }

    // ---- final: symbols for t=127, hf/cf ----
    if ((cta & 31) == 0 && tid < 32) {
        int b = b0 + tid;
        unsigned long long key = g_amax[1][b];
        out[OUT_SYM + b * TT + 127] = (float)(~(unsigned)key & 1023u);
    }
    {
        int base = cta * 1024 + tid * 2;
#pragma unroll
        for (int q = 0; q < 2; q++) {
            out[OUT_HF + base + q] = g_hd[0][base + q];
            out[OUT_CF + base + q] = g_cd[base + q];
        }
    }
}

// ---------------- launcher ----------------
extern "C" void kernel_launch(void* const* d_in, const int* in_sizes, int n_in,
                              void* d_out, int out_size) {
    const void*  inputs = d_in[0];
    const float* emb    = (const float*)d_in[1];
    const float* eWih   = (const float*)d_in[2];
    const float* eWhh   = (const float*)d_in[3];
    const float* eb     = (const float*)d_in[4];
    const float* dWih   = (const float*)d_in[5];
    const float* dWhh   = (const float*)d_in[6];
    const float* db     = (const float*)d_in[7];
    const float* fcW    = (const float*)d_in[8];
    const float* fcb    = (const float*)d_in[9];
    float* out = (float*)d_out;

    detect_kernel<<<1, 32>>>(inputs);
    table_dec_kernel<<<dim3(64, 16), 256>>>(emb, dWih, db);
    table_pre_kernel<<<dim3(64, 2), 256>>>(emb, eWih, eb, inputs);
    main_kernel<<<NCTA, NTHR>>>(inputs, eWhh, dWhh, fcW, fcb, out);
}

// round 9
// speedup vs baseline: 1.2517x; 1.2517x over previous
#include <cuda_runtime.h>
#include <cuda_bf16.h>
#include <math.h>

// Problem dims
#define BB 128
#define TT 128
#define VV 1024
#define EE 512
#define HH 1024
#define GG 4096   // 4*H

// d_out layout (floats): decoder_outputs [B,T,H], hf [B,H], cf [B,H], symbols [B,T]
#define OUT_DEC 0
#define OUT_HF  (BB*TT*HH)
#define OUT_CF  (OUT_HF + BB*HH)
#define OUT_SYM (OUT_CF + BB*HH)

#define NCTA 128
#define NTHR 512

// ---------------- scratch (static device memory) ----------------
__device__ float g_dec_table[VV * GG];      // emb @ dec_W_ih^T + dec_b
__device__ float g_pregates_enc[TT * GG];   // row-127 enc input pregates
__device__ float g_he[2][HH];
__device__ float g_ce[HH];
__device__ float g_hd[2][BB * HH];          // decoder h, [b][k], double buffered
__device__ float g_cd[BB * HH];             // decoder c, [b][j]
__device__ unsigned long long g_amax[2][BB];
__device__ int   g_idx64;
__device__ unsigned g_bar_count = 0;
__device__ unsigned g_bar_gen = 0;

// ---------------- helpers ----------------
__device__ __forceinline__ int read_idx(const void* p, int i) {
    if (g_idx64) return (int)((const long long*)p)[i];
    return ((const int*)p)[i];
}
__device__ __forceinline__ float sigf(float x) { return 1.0f / (1.0f + expf(-x)); }

__device__ __forceinline__ void ffma2(unsigned long long& d, unsigned long long a, unsigned long long b) {
    asm("fma.rn.f32x2 %0, %1, %2, %0;" : "+l"(d) : "l"(a), "l"(b));
}
__device__ __forceinline__ unsigned long long dupf(float x) {
    unsigned long long r; unsigned u = __float_as_uint(x);
    asm("mov.b64 %0, {%1, %1};" : "=l"(r) : "r"(u));
    return r;
}
__device__ __forceinline__ float lo2(unsigned long long p) { return __uint_as_float((unsigned)p); }
__device__ __forceinline__ float hi2(unsigned long long p) { return __uint_as_float((unsigned)(p >> 32)); }
__device__ __forceinline__ unsigned monof(float v) {
    unsigned b = __float_as_uint(v);
    return b ^ ((b & 0x80000000u) ? 0xFFFFFFFFu : 0x80000000u);
}

// grid barrier: release/acquire gpu scope (all 128 CTAs resident: 1 per SM)
__device__ __forceinline__ void grid_bar() {
    __syncthreads();
    if (threadIdx.x == 0) {
        unsigned gen;
        asm volatile("ld.acquire.gpu.u32 %0, [%1];" : "=r"(gen) : "l"(&g_bar_gen));
        unsigned old;
        asm volatile("atom.add.release.gpu.u32 %0, [%1], 1;" : "=r"(old) : "l"(&g_bar_count));
        if (old == NCTA - 1) {
            g_bar_count = 0;
            asm volatile("st.release.gpu.u32 [%0], %1;" :: "l"(&g_bar_gen), "r"(gen + 1));
        } else {
            unsigned cur;
            do {
                asm volatile("ld.acquire.gpu.u32 %0, [%1];" : "=r"(cur) : "l"(&g_bar_gen));
            } while (cur == gen);
        }
    }
    __syncthreads();
}

// Detect input index dtype
__global__ void detect_kernel(const void* p) {
    if (threadIdx.x == 0) {
        const unsigned long long* q = (const unsigned long long*)p;
        int ok = 1;
        for (int i = 0; i < 8; i++) if (q[i] > 1023ull) ok = 0;
        g_idx64 = ok;
    }
}

// ---------------- table GEMM (one-time) — unchanged (bit-exact lineage) ----------------
__device__ __forceinline__ void table_gemm_body(
    const float* __restrict__ A, const float* __restrict__ W,
    const float* __restrict__ bias, float* __restrict__ C,
    int K, const void* map, int map_off)
{
    __shared__ __align__(16) float Ash[16][68];
    __shared__ __align__(16) float Bsh[16][68];
    int tid = threadIdx.x;
    int tm = tid & 15, tn = tid >> 4;
    int n0 = blockIdx.x * 64, m0 = blockIdx.y * 64;

    int r  = tid >> 2;
    int kf = (tid & 3) << 2;
    int am = m0 + r;
    int arow = am;
    if (map) arow = read_idx(map, map_off + am);
    const float* Aptr = A + (size_t)arow * K;
    const float* Wptr = W + (size_t)(n0 + r) * K;

    unsigned long long accp[4][2];
#pragma unroll
    for (int i = 0; i < 4; i++) { accp[i][0] = 0ull; accp[i][1] = 0ull; }

    for (int k0 = 0; k0 < K; k0 += 16) {
        float4 av = *(const float4*)(Aptr + k0 + kf);
        float4 bv = *(const float4*)(Wptr + k0 + kf);
        __syncthreads();
        Ash[kf+0][r] = av.x; Ash[kf+1][r] = av.y; Ash[kf+2][r] = av.z; Ash[kf+3][r] = av.w;
        Bsh[kf+0][r] = bv.x; Bsh[kf+1][r] = bv.y; Bsh[kf+2][r] = bv.z; Bsh[kf+3][r] = bv.w;
        __syncthreads();
#pragma unroll
        for (int k = 0; k < 16; k++) {
            float4 a4 = *(const float4*)&Ash[k][tm * 4];
            ulonglong2 b01 = *(const ulonglong2*)&Bsh[k][tn * 4];
            unsigned long long a0 = dupf(a4.x), a1 = dupf(a4.y), a2 = dupf(a4.z), a3 = dupf(a4.w);
            ffma2(accp[0][0], b01.x, a0); ffma2(accp[0][1], b01.y, a0);
            ffma2(accp[1][0], b01.x, a1); ffma2(accp[1][1], b01.y, a1);
            ffma2(accp[2][0], b01.x, a2); ffma2(accp[2][1], b01.y, a2);
            ffma2(accp[3][0], b01.x, a3); ffma2(accp[3][1], b01.y, a3);
        }
    }
#pragma unroll
    for (int i = 0; i < 4; i++) {
        int m = m0 + tm * 4 + i;
#pragma unroll
        for (int p = 0; p < 2; p++) {
            int n = n0 + tn * 4 + p * 2;
            C[(size_t)m * GG + n]     = lo2(accp[i][p]) + bias[n];
            C[(size_t)m * GG + n + 1] = hi2(accp[i][p]) + bias[n + 1];
        }
    }
}

__global__ __launch_bounds__(256) void table_dec_kernel(
    const float* __restrict__ emb, const float* __restrict__ W, const float* __restrict__ bias)
{
    table_gemm_body(emb, W, bias, g_dec_table, EE, nullptr, 0);
}
__global__ __launch_bounds__(256) void table_pre_kernel(
    const float* __restrict__ emb, const float* __restrict__ W, const float* __restrict__ bias,
    const void* __restrict__ inputs)
{
    table_gemm_body(emb, W, bias, g_pregates_enc, EE, inputs, 127 * TT);
}

// ---------------- persistent main kernel (producer/consumer) ----------------
// smem layout (floats):
//   wbuf: double-buffered w tiles, 2 x 128x33 at offsets 0 / 4224  (gates)
//         fc reuses as 2 x 32x33 at offsets 0 / 1056
//   gsh:  gate pre-activation staging [128][34] aliases wbuf (dead at staging)
//   hbuf: double-buffered h^T chunks, 2 x 32x36 at offsets 8448 / 9600
#define WBUF_OFF  0
#define WBUF_STRIDE 4224
#define WBUF_STRIDE_FC 1056
#define HBUF_OFF  8448
#define HBUF_STRIDE 1152

struct MainSmem {
    __align__(16) float buf[10752];   // 43 KB
    int ssym[32];
};

__global__ __launch_bounds__(NTHR, 1) void main_kernel(
    const void* __restrict__ inputs,
    const float* __restrict__ eWhh,
    const float* __restrict__ dWhh,
    const float* __restrict__ fcW,
    const float* __restrict__ fcb,
    float* __restrict__ out)
{
    __shared__ MainSmem smem;
    const int cta = blockIdx.x;
    const int tid = threadIdx.x;
    const bool cons = tid < 256;         // warps 0-7 consumers, 8-15 producers
    const int ptid = tid & 255;          // producer-local id

    // ---- phase 0: zero encoder state ----
    if (cta == 0) {
        for (int i = tid; i < HH; i += NTHR) { g_he[0][i] = 0.0f; g_ce[i] = 0.0f; }
    }
    grid_bar();

    // ---- encoder: batch row 127 only (first 8 warps compute; all hit grid_bar) ----
    {
        const int wid = tid >> 5, lane = tid & 31;
        const int j = cta * 8 + wid;
        const float* w = eWhh + (size_t)j * HH;
        for (int t = 0; t < TT; t++) {
            if (wid < 8) {
                const float* hin = g_he[t & 1];
                float a0 = 0.f, a1 = 0.f, a2 = 0.f, a3 = 0.f;
#pragma unroll 4
                for (int k = lane; k < HH; k += 32) {
                    float hv = hin[k];
                    a0 += hv * w[k];
                    a1 += hv * w[1024 * 1024 + k];
                    a2 += hv * w[2 * 1024 * 1024 + k];
                    a3 += hv * w[3 * 1024 * 1024 + k];
                }
#pragma unroll
                for (int o = 16; o; o >>= 1) {
                    a0 += __shfl_xor_sync(0xffffffffu, a0, o);
                    a1 += __shfl_xor_sync(0xffffffffu, a1, o);
                    a2 += __shfl_xor_sync(0xffffffffu, a2, o);
                    a3 += __shfl_xor_sync(0xffffffffu, a3, o);
                }
                if (lane == 0) {
                    const float* pg = g_pregates_enc + (size_t)t * GG;
                    float gi = a0 + pg[j];
                    float gf = a1 + pg[HH + j];
                    float gg = a2 + pg[2 * HH + j];
                    float go = a3 + pg[3 * HH + j];
                    float i_ = sigf(gi), f_ = sigf(gf), c_ = tanhf(gg), o_ = sigf(go);
                    float c = f_ * g_ce[j] + i_ * c_;
                    g_ce[j] = c;
                    g_he[(t + 1) & 1][j] = o_ * tanhf(c);
                }
            }
            grid_bar();
        }
    }

    // ---- decoder init ----
    {
        int base = cta * 1024 + tid * 2;
#pragma unroll
        for (int q = 0; q < 2; q++) {
            int k = tid * 2 + q;
            g_hd[0][base + q] = (cta == 127) ? g_he[0][k] : 0.0f;
            g_cd[base + q]    = (cta == 127) ? g_ce[k]    : 0.0f;
        }
    }
    grid_bar();

    // ---- decoder: 128 steps ----
    const int j0 = (cta & 31) * 32;          // gates j-tile / fc n-tile
    const int b0 = (cta >> 5) * 32;          // b-tile

    // consumer gates mapping: thread owns cols {cA, cA+64} x 8 b's
    const int cA = tid & 63;                 // 0..63 (consumer)
    const int bo = tid >> 6;                 // 0..3 warp-uniform (consumer)
    // consumer fc mapping: n = lane, 4 b's
    const int fn = tid & 31;
    const int bg = tid >> 5;                 // 0..7 warp-uniform (consumer)
    // producer h mapping
    const int phb = ptid >> 3;               // 0..31
    const int phk = (ptid & 7) << 2;

    float* buf = smem.buf;
    float* gsh = smem.buf;                   // staging aliases w buffers

    for (int t = 0; t < TT; t++) {
        // ===== gates phase: pregate = dec_table[sym] + h @ W_hh^T =====
        {
            const float* hin = g_hd[t & 1];
            float* hout = g_hd[(t + 1) & 1];

            if (tid < 32) {
                int b = b0 + tid;
                int s;
                if (t == 0) {
                    s = read_idx(inputs, b * TT);
                } else {
                    unsigned long long key = g_amax[(t - 1) & 1][b];
                    s = (int)(~(unsigned)key & 1023u);
                    if ((cta & 31) == 0) out[OUT_SYM + b * TT + (t - 1)] = (float)s;
                }
                smem.ssym[tid] = s;
            }
            if (cta == 0 && tid < BB) g_amax[t & 1][tid] = 0ull;

            // prologue: producers fill buffer 0 (chunk 0)
            if (!cons) {
#pragma unroll
                for (int i = 0; i < 4; i++) {
                    int q = i * 256 + ptid;
                    int c = q >> 3; int ks = (q & 7) << 2;
                    int g = c >> 5, jj = c & 31;
                    float4 v = *(const float4*)(dWhh + ((size_t)(g * HH + j0 + jj)) * HH + ks);
                    float* p = buf + WBUF_OFF + c * 33 + ks;
                    p[0] = v.x; p[1] = v.y; p[2] = v.z; p[3] = v.w;
                }
                {
                    float4 v = *(const float4*)(hin + (size_t)(b0 + phb) * HH + phk);
                    float* p = buf + HBUF_OFF + phk * 36 + phb;
                    p[0] = v.x; p[36] = v.y; p[72] = v.z; p[108] = v.w;
                }
            }
            __syncthreads();

            unsigned long long acc[2][4];
#pragma unroll
            for (int i = 0; i < 4; i++) { acc[0][i] = 0ull; acc[1][i] = 0ull; }

            for (int ch = 0; ch < 32; ch++) {
                if (cons) {
                    const float* wt = buf + WBUF_OFF + (ch & 1) * WBUF_STRIDE;
                    const float* hb = buf + HBUF_OFF + (ch & 1) * HBUF_STRIDE + bo * 8;
                    const float* w0p = wt + cA * 33;
                    const float* w1p = wt + (cA + 64) * 33;
#pragma unroll
                    for (int k = 0; k < 32; k++) {
                        ulonglong2 h01 = *(const ulonglong2*)(hb + k * 36);
                        ulonglong2 h23 = *(const ulonglong2*)(hb + k * 36 + 4);
                        unsigned long long w0 = dupf(w0p[k]);
                        unsigned long long w1 = dupf(w1p[k]);
                        ffma2(acc[0][0], h01.x, w0); ffma2(acc[0][1], h01.y, w0);
                        ffma2(acc[0][2], h23.x, w0); ffma2(acc[0][3], h23.y, w0);
                        ffma2(acc[1][0], h01.x, w1); ffma2(acc[1][1], h01.y, w1);
                        ffma2(acc[1][2], h23.x, w1); ffma2(acc[1][3], h23.y, w1);
                    }
                } else if (ch < 31) {
                    int k0 = (ch + 1) * 32;
                    float* wt = buf + WBUF_OFF + ((ch + 1) & 1) * WBUF_STRIDE;
                    float* hbw = buf + HBUF_OFF + ((ch + 1) & 1) * HBUF_STRIDE;
#pragma unroll
                    for (int i = 0; i < 4; i++) {
                        int q = i * 256 + ptid;
                        int c = q >> 3; int ks = (q & 7) << 2;
                        int g = c >> 5, jj = c & 31;
                        float4 v = *(const float4*)(dWhh + ((size_t)(g * HH + j0 + jj)) * HH + k0 + ks);
                        float* p = wt + c * 33 + ks;
                        p[0] = v.x; p[1] = v.y; p[2] = v.z; p[3] = v.w;
                    }
                    {
                        float4 v = *(const float4*)(hin + (size_t)(b0 + phb) * HH + k0 + phk);
                        float* p = hbw + phk * 36 + phb;
                        p[0] = v.x; p[36] = v.y; p[72] = v.z; p[108] = v.w;
                    }
                }
                __syncthreads();
            }

            // stage pre-activations [col][b] (w buffers dead)
            if (cons) {
#pragma unroll
                for (int bp = 0; bp < 4; bp++) {
                    *(unsigned long long*)(gsh + cA * 34 + bo * 8 + 2 * bp)        = acc[0][bp];
                    *(unsigned long long*)(gsh + (cA + 64) * 34 + bo * 8 + 2 * bp) = acc[1][bp];
                }
            }
            __syncthreads();

            // LSTM epilogue: 512 threads, each 2 b's
            {
                int jj = tid & 31;
                int grp = tid >> 5;               // 0..15
                int jg = j0 + jj;
#pragma unroll
                for (int i = 0; i < 2; i++) {
                    int b = grp * 2 + i;
                    int s = smem.ssym[b];
                    const float* tb = g_dec_table + (size_t)s * GG + jg;
                    float gi = gsh[(0 * 32 + jj) * 34 + b] + tb[0];
                    float gf = gsh[(1 * 32 + jj) * 34 + b] + tb[HH];
                    float gg = gsh[(2 * 32 + jj) * 34 + b] + tb[2 * HH];
                    float go = gsh[(3 * 32 + jj) * 34 + b] + tb[3 * HH];
                    float i_ = sigf(gi), f_ = sigf(gf), c_ = tanhf(gg), o_ = sigf(go);
                    int off = (b0 + b) * HH + jg;
                    float c = f_ * g_cd[off] + i_ * c_;
                    g_cd[off] = c;
                    hout[off] = o_ * tanhf(c);
                }
            }
        }
        grid_bar();

        // ===== fc phase: logits = h @ fc_W^T + fc_b; write + argmax =====
        {
            const float* h = g_hd[(t + 1) & 1];

            // prologue: producers fill buffer 0
            if (!cons) {
                {
                    int n = ptid >> 3; int ks = (ptid & 7) << 2;
                    float4 v = *(const float4*)(fcW + (size_t)(j0 + n) * HH + ks);
                    float* p = buf + WBUF_OFF + n * 33 + ks;
                    p[0] = v.x; p[1] = v.y; p[2] = v.z; p[3] = v.w;
                }
                {
                    float4 v = *(const float4*)(h + (size_t)(b0 + phb) * HH + phk);
                    float* p = buf + HBUF_OFF + phk * 36 + phb;
                    p[0] = v.x; p[36] = v.y; p[72] = v.z; p[108] = v.w;
                }
            }
            __syncthreads();

            unsigned long long a0 = 0ull, a1 = 0ull;

            for (int ch = 0; ch < 32; ch++) {
                if (cons) {
                    const float* wp = buf + WBUF_OFF + (ch & 1) * WBUF_STRIDE_FC + fn * 33;
                    const float* hb = buf + HBUF_OFF + (ch & 1) * HBUF_STRIDE + bg * 4;
#pragma unroll
                    for (int k = 0; k < 32; k++) {
                        ulonglong2 hp = *(const ulonglong2*)(hb + k * 36);
                        unsigned long long wd = dupf(wp[k]);
                        ffma2(a0, hp.x, wd);
                        ffma2(a1, hp.y, wd);
                    }
                } else if (ch < 31) {
                    int k0 = (ch + 1) * 32;
                    float* wt = buf + WBUF_OFF + ((ch + 1) & 1) * WBUF_STRIDE_FC;
                    float* hbw = buf + HBUF_OFF + ((ch + 1) & 1) * HBUF_STRIDE;
                    {
                        int n = ptid >> 3; int ks = (ptid & 7) << 2;
                        float4 v = *(const float4*)(fcW + (size_t)(j0 + n) * HH + k0 + ks);
                        float* p = wt + n * 33 + ks;
                        p[0] = v.x; p[1] = v.y; p[2] = v.z; p[3] = v.w;
                    }
                    {
                        float4 v = *(const float4*)(h + (size_t)(b0 + phb) * HH + k0 + phk);
                        float* p = hbw + phk * 36 + phb;
                        p[0] = v.x; p[36] = v.y; p[72] = v.z; p[108] = v.w;
                    }
                }
                __syncthreads();
            }

            if (cons) {
                int n = j0 + fn;
                float bias = fcb[n];
                float v[4] = { lo2(a0) + bias, hi2(a0) + bias, lo2(a1) + bias, hi2(a1) + bias };
#pragma unroll
                for (int i = 0; i < 4; i++) {
                    int b = b0 + bg * 4 + i;
                    out[OUT_DEC + (size_t)b * TT * HH + (size_t)t * HH + n] = v[i];
                }
#pragma unroll
                for (int i = 0; i < 4; i++) {
                    unsigned long long key =
                        ((unsigned long long)monof(v[i]) << 32) | (unsigned)(~(unsigned)n);
#pragma unroll
                    for (int off = 16; off; off >>= 1) {
                        unsigned long long o = __shfl_xor_sync(0xffffffffu, key, off);
                        if (o > key) key = o;
                    }
                    if (fn == 0) atomicMax(&g_amax[t & 1][b0 + bg * 4 + i], key);
                }
            }
        }
        grid_bar();
    }

    // ---- final: symbols for t=127, hf/cf ----
    if ((cta & 31) == 0 && tid < 32) {
        int b = b0 + tid;
        unsigned long long key = g_amax[1][b];
        out[OUT_SYM + b * TT + 127] = (float)(~(unsigned)key & 1023u);
    }
    {
        int base = cta * 1024 + tid * 2;
#pragma unroll
        for (int q = 0; q < 2; q++) {
            out[OUT_HF + base + q] = g_hd[0][base + q];
            out[OUT_CF + base + q] = g_cd[base + q];
        }
    }
}

// ---------------- launcher ----------------
extern "C" void kernel_launch(void* const* d_in, const int* in_sizes, int n_in,
                              void* d_out, int out_size) {
    const void*  inputs = d_in[0];
    const float* emb    = (const float*)d_in[1];
    const float* eWih   = (const float*)d_in[2];
    const float* eWhh   = (const float*)d_in[3];
    const float* eb     = (const float*)d_in[4];
    const float* dWih   = (const float*)d_in[5];
    const float* dWhh   = (const float*)d_in[6];
    const float* db     = (const float*)d_in[7];
    const float* fcW    = (const float*)d_in[8];
    const float* fcb    = (const float*)d_in[9];
    float* out = (float*)d_out;

    detect_kernel<<<1, 32>>>(inputs);
    table_dec_kernel<<<dim3(64, 16), 256>>>(emb, dWih, db);
    table_pre_kernel<<<dim3(64, 2), 256>>>(emb, eWih, eb, inputs);
    main_kernel<<<NCTA, NTHR>>>(inputs, eWhh, dWhh, fcW, fcb, out);
}